// round 2
// baseline (speedup 1.0000x reference)
#include <cuda_runtime.h>
#include <math.h>

// Problem constants
#define B_   2
#define TX_  1024
#define TY_  4096
#define C_   768
#define H_   12
#define D_   64

// Scratch (device globals: no allocation allowed)
__device__ float g_q[B_ * TX_ * C_];
__device__ float g_k[B_ * TY_ * C_];
__device__ float g_v[B_ * TY_ * C_];
__device__ float g_o[B_ * TX_ * C_];

// ---------------------------------------------------------------------------
// Generic tiled fp32 GEMM: out = A[M,K] @ W[K,N], M/N multiples of 64, K of 16.
// Block = 64x64 tile, 256 threads, 4x4 micro-tile per thread.
// If out1 != nullptr, columns [0,splitN) go to out0 (width splitN) and
// columns [splitN,N) go to out1 (width N-splitN).
// ---------------------------------------------------------------------------
__global__ __launch_bounds__(256) void gemm_kernel(
    const float* __restrict__ A, const float* __restrict__ W,
    float* __restrict__ out0, float* __restrict__ out1,
    int N, int K, int splitN)
{
    __shared__ float As[16][68];  // [k][m], padded, 16B-aligned rows (68*4=272)
    __shared__ float Bs[16][64];  // [k][n]

    const int tid = threadIdx.x;
    const int tx = tid & 15, ty = tid >> 4;
    const int bn = blockIdx.x * 64, bm = blockIdx.y * 64;

    const int arow = tid >> 2, akq = (tid & 3) * 4;
    const int brow = tid >> 4, bcol = (tid & 15) * 4;

    float acc[4][4] = {};

    for (int k0 = 0; k0 < K; k0 += 16) {
        float4 av = *(const float4*)&A[(size_t)(bm + arow) * K + k0 + akq];
        float4 bv = *(const float4*)&W[(size_t)(k0 + brow) * N + bn + bcol];
        As[akq + 0][arow] = av.x;
        As[akq + 1][arow] = av.y;
        As[akq + 2][arow] = av.z;
        As[akq + 3][arow] = av.w;
        *(float4*)&Bs[brow][bcol] = bv;
        __syncthreads();
#pragma unroll
        for (int kk = 0; kk < 16; kk++) {
            float4 a = *(const float4*)&As[kk][ty * 4];
            float4 b = *(const float4*)&Bs[kk][tx * 4];
            acc[0][0] += a.x * b.x; acc[0][1] += a.x * b.y; acc[0][2] += a.x * b.z; acc[0][3] += a.x * b.w;
            acc[1][0] += a.y * b.x; acc[1][1] += a.y * b.y; acc[1][2] += a.y * b.z; acc[1][3] += a.y * b.w;
            acc[2][0] += a.z * b.x; acc[2][1] += a.z * b.y; acc[2][2] += a.z * b.z; acc[2][3] += a.z * b.w;
            acc[3][0] += a.w * b.x; acc[3][1] += a.w * b.y; acc[3][2] += a.w * b.z; acc[3][3] += a.w * b.w;
        }
        __syncthreads();
    }

    const int col = bn + tx * 4;
#pragma unroll
    for (int i = 0; i < 4; i++) {
        const int row = bm + ty * 4 + i;
        float4 r = make_float4(acc[i][0], acc[i][1], acc[i][2], acc[i][3]);
        if (out1) {
            if (col < splitN)
                *(float4*)&out0[(size_t)row * splitN + col] = r;
            else
                *(float4*)&out1[(size_t)row * (N - splitN) + (col - splitN)] = r;
        } else {
            *(float4*)&out0[(size_t)row * N + col] = r;
        }
    }
}

// ---------------------------------------------------------------------------
// Interleaved RoPE, in place. One block per row (B*T rows), 384 threads =
// C/2 pairs. pair index within head = pr % 32 (D/2 = 32).
//   out[2p]   = t[2p]*cos(f) - t[2p+1]*sin(f)
//   out[2p+1] = t[2p+1]*cos(f) + t[2p]*sin(f),  f = pos * inv_freq[p]
// ---------------------------------------------------------------------------
__global__ __launch_bounds__(384) void rope_kernel(
    float* __restrict__ t, const float* __restrict__ pos,
    const float* __restrict__ inv_freq)
{
    const int row = blockIdx.x;
    const int pr = threadIdx.x;  // 0..383
    const float p = pos[row];
    const float f = p * inv_freq[pr & 31];
    float s, c;
    sincosf(f, &s, &c);
    float2 v = *(float2*)&t[(size_t)row * C_ + pr * 2];
    float2 o;
    o.x = v.x * c - v.y * s;
    o.y = v.y * c + v.x * s;
    *(float2*)&t[(size_t)row * C_ + pr * 2] = o;
}

// ---------------------------------------------------------------------------
// Banded flash-attention. Block = (b, h, 64-query tile), 256 threads (16x16),
// 4x4 micro-tiles. Key band found by binary search on sorted y_t; exact
// per-element masking inside.
// Dynamic smem: Qs[d][q], Ks[d][k], Vs[k][d], Ps[q][k], each 64x68 floats.
// ---------------------------------------------------------------------------
#define ATTN_SMEM (4 * 64 * 68 * 4)

__global__ __launch_bounds__(256) void attn_kernel(
    const float* __restrict__ xt_g, const float* __restrict__ yt_g,
    const int* __restrict__ p_dist, const int* __restrict__ p_mind)
{
    extern __shared__ float sm[];
    float(*Qs)[68] = (float(*)[68])sm;                 // [d][q]
    float(*Ks)[68] = (float(*)[68])(sm + 64 * 68);     // [d][k]
    float(*Vs)[68] = (float(*)[68])(sm + 2 * 64 * 68); // [k][d]
    float(*Ps)[68] = (float(*)[68])(sm + 3 * 64 * 68); // [q][k]
    __shared__ float sxt[64], syt[64];
    __shared__ int s_lo, s_hi;

    const int b = blockIdx.z, h = blockIdx.y, q0 = blockIdx.x * 64;
    const int tid = threadIdx.x;
    const int tx = tid & 15, ty = tid >> 4;

    const float fdist = (float)p_dist[0];
    const float fmind = (float)p_mind[0];
    const float* yt = yt_g + (size_t)b * TY_;

    if (tid < 64) sxt[tid] = xt_g[b * TX_ + q0 + tid];

    // Load Q tile transposed: Qs[d][r]
    const float* qbase = g_q + ((size_t)(b * TX_ + q0)) * C_ + h * D_;
#pragma unroll
    for (int i = 0; i < 4; i++) {
        int idx = tid + i * 256;
        int r = idx >> 4, d4 = (idx & 15) * 4;
        float4 v = *(const float4*)&qbase[(size_t)r * C_ + d4];
        Qs[d4 + 0][r] = v.x; Qs[d4 + 1][r] = v.y;
        Qs[d4 + 2][r] = v.z; Qs[d4 + 3][r] = v.w;
    }

    if (tid == 0) {
        // band: y_t in [xt_min - dist, xt_max], xt = x_t - min_dist
        float xlo = xt_g[b * TX_ + q0] - fmind - fdist;
        float xhi = xt_g[b * TX_ + q0 + 63] - fmind;
        int lo = 0, hi = TY_;
        while (lo < hi) { int m = (lo + hi) >> 1; if (yt[m] < xlo) lo = m + 1; else hi = m; }
        s_lo = lo;
        int lo2 = lo, hi2 = TY_;
        while (lo2 < hi2) { int m = (lo2 + hi2) >> 1; if (yt[m] <= xhi) lo2 = m + 1; else hi2 = m; }
        s_hi = lo2;
    }
    __syncthreads();

    float accO[4][4] = {};
    float m_i[4] = {-1e30f, -1e30f, -1e30f, -1e30f};
    float l_i[4] = {};

    const float* kbase = g_k + ((size_t)b * TY_) * C_ + h * D_;
    const float* vbase = g_v + ((size_t)b * TY_) * C_ + h * D_;

    const int kstart = s_lo & ~63;
    const int kend = s_hi;

    for (int k0 = kstart; k0 < kend; k0 += 64) {
        if (tid < 64) syt[tid] = yt[k0 + tid];
#pragma unroll
        for (int i = 0; i < 4; i++) {
            int idx = tid + i * 256;
            int r = idx >> 4, d4 = (idx & 15) * 4;
            size_t go = (size_t)(k0 + r) * C_ + d4;
            float4 kv = *(const float4*)&kbase[go];
            Ks[d4 + 0][r] = kv.x; Ks[d4 + 1][r] = kv.y;
            Ks[d4 + 2][r] = kv.z; Ks[d4 + 3][r] = kv.w;
            float4 vv = *(const float4*)&vbase[go];
            *(float4*)&Vs[r][d4] = vv;
        }
        __syncthreads();

        // S = Q K^T for this 64x64 tile
        float s4[4][4] = {};
#pragma unroll
        for (int d = 0; d < 64; d++) {
            float4 a = *(const float4*)&Qs[d][ty * 4];
            float4 bb = *(const float4*)&Ks[d][tx * 4];
            s4[0][0] += a.x * bb.x; s4[0][1] += a.x * bb.y; s4[0][2] += a.x * bb.z; s4[0][3] += a.x * bb.w;
            s4[1][0] += a.y * bb.x; s4[1][1] += a.y * bb.y; s4[1][2] += a.y * bb.z; s4[1][3] += a.y * bb.w;
            s4[2][0] += a.z * bb.x; s4[2][1] += a.z * bb.y; s4[2][2] += a.z * bb.z; s4[2][3] += a.z * bb.w;
            s4[3][0] += a.w * bb.x; s4[3][1] += a.w * bb.y; s4[3][2] += a.w * bb.z; s4[3][3] += a.w * bb.w;
        }

        // mask + online softmax
#pragma unroll
        for (int i = 0; i < 4; i++) {
            const float xti = sxt[ty * 4 + i] - fmind;
            float rmax = -1e30f;
            float pv[4];
#pragma unroll
            for (int j = 0; j < 4; j++) {
                float ytj = syt[tx * 4 + j];
                bool valid = (xti >= ytj) && (xti <= ytj + fdist);
                float v = valid ? s4[i][j] * 0.125f : -1e30f;
                s4[i][j] = v;
                rmax = fmaxf(rmax, v);
            }
#pragma unroll
            for (int off = 8; off; off >>= 1)
                rmax = fmaxf(rmax, __shfl_xor_sync(0xffffffffu, rmax, off));
            const float mnew = fmaxf(m_i[i], rmax);
            const float alpha = __expf(m_i[i] - mnew);
            m_i[i] = mnew;
            float rs = 0.f;
#pragma unroll
            for (int j = 0; j < 4; j++) {
                float p = __expf(s4[i][j] - mnew);
                pv[j] = p;
                rs += p;
            }
#pragma unroll
            for (int off = 8; off; off >>= 1)
                rs += __shfl_xor_sync(0xffffffffu, rs, off);
            l_i[i] = l_i[i] * alpha + rs;
#pragma unroll
            for (int j = 0; j < 4; j++) accO[i][j] *= alpha;
            *(float4*)&Ps[ty * 4 + i][tx * 4] = make_float4(pv[0], pv[1], pv[2], pv[3]);
        }
        __syncthreads();

        // O += P @ V
#pragma unroll 16
        for (int k = 0; k < 64; k++) {
            float4 vv = *(const float4*)&Vs[k][tx * 4];
            float a0 = Ps[ty * 4 + 0][k];
            float a1 = Ps[ty * 4 + 1][k];
            float a2 = Ps[ty * 4 + 2][k];
            float a3 = Ps[ty * 4 + 3][k];
            accO[0][0] += a0 * vv.x; accO[0][1] += a0 * vv.y; accO[0][2] += a0 * vv.z; accO[0][3] += a0 * vv.w;
            accO[1][0] += a1 * vv.x; accO[1][1] += a1 * vv.y; accO[1][2] += a1 * vv.z; accO[1][3] += a1 * vv.w;
            accO[2][0] += a2 * vv.x; accO[2][1] += a2 * vv.y; accO[2][2] += a2 * vv.z; accO[2][3] += a2 * vv.w;
            accO[3][0] += a3 * vv.x; accO[3][1] += a3 * vv.y; accO[3][2] += a3 * vv.z; accO[3][3] += a3 * vv.w;
        }
        __syncthreads();
    }

    // epilogue: normalize by l, write to g_o
    float* obase = g_o + ((size_t)(b * TX_ + q0)) * C_ + h * D_;
#pragma unroll
    for (int i = 0; i < 4; i++) {
        float inv = 1.f / l_i[i];
        float4 r = make_float4(accO[i][0] * inv, accO[i][1] * inv,
                               accO[i][2] * inv, accO[i][3] * inv);
        *(float4*)&obase[(size_t)(ty * 4 + i) * C_ + tx * 4] = r;
    }
}

// ---------------------------------------------------------------------------
// Launch
// inputs: 0 x, 1 x_t, 2 y, 3 y_t, 4 dist, 5 min_dist, 6 Wq, 7 Wkv, 8 Wproj, 9 inv_freq
// ---------------------------------------------------------------------------
extern "C" void kernel_launch(void* const* d_in, const int* in_sizes, int n_in,
                              void* d_out, int out_size)
{
    const float* x        = (const float*)d_in[0];
    const float* x_t      = (const float*)d_in[1];
    const float* y        = (const float*)d_in[2];
    const float* y_t      = (const float*)d_in[3];
    const int*   dist     = (const int*)d_in[4];
    const int*   mind     = (const int*)d_in[5];
    const float* Wq       = (const float*)d_in[6];
    const float* Wkv      = (const float*)d_in[7];
    const float* Wproj    = (const float*)d_in[8];
    const float* inv_freq = (const float*)d_in[9];
    float* out = (float*)d_out;

    float *q_p, *k_p, *v_p, *o_p;
    cudaGetSymbolAddress((void**)&q_p, g_q);
    cudaGetSymbolAddress((void**)&k_p, g_k);
    cudaGetSymbolAddress((void**)&v_p, g_v);
    cudaGetSymbolAddress((void**)&o_p, g_o);

    cudaFuncSetAttribute(attn_kernel, cudaFuncAttributeMaxDynamicSharedMemorySize, ATTN_SMEM);

    // q = x @ Wq   [2048,768] x [768,768]
    gemm_kernel<<<dim3(C_ / 64, (B_ * TX_) / 64), 256>>>(x, Wq, q_p, nullptr, C_, C_, 0);
    // kv = y @ Wkv [8192,768] x [768,1536] -> split into k, v
    gemm_kernel<<<dim3(2 * C_ / 64, (B_ * TY_) / 64), 256>>>(y, Wkv, k_p, v_p, 2 * C_, C_, C_);
    // RoPE
    rope_kernel<<<B_ * TX_, 384>>>(q_p, x_t, inv_freq);
    rope_kernel<<<B_ * TY_, 384>>>(k_p, y_t, inv_freq);
    // banded flash attention
    attn_kernel<<<dim3(TX_ / 64, H_, B_), 256, ATTN_SMEM>>>(x_t, y_t, dist, mind);
    // final projection: out = o @ Wproj
    gemm_kernel<<<dim3(C_ / 64, (B_ * TX_) / 64), 256>>>(o_p, Wproj, out, nullptr, C_, C_, 0);
}